// round 6
// baseline (speedup 1.0000x reference)
#include <cuda_runtime.h>

#define BB 256
#define SS 4096
#define HH 64
#define NG 256   // 4*H gates

// Scratch (allocation-free: static device globals)
__device__ float g_buf0[(size_t)BB * SS * HH];
__device__ float g_buf1[(size_t)BB * SS * HH];
__device__ float g_xg[(size_t)BB * SS * NG];   // gate-interleaved: [b,s,hh*4+q]

typedef unsigned long long ull;

// ---- packed f32x2 helpers (FFMA2 path, sm_103a) ----
__device__ __forceinline__ ull pk2(float lo, float hi) {
    ull r; asm("mov.b64 %0,{%1,%2};" : "=l"(r) : "f"(lo), "f"(hi)); return r;
}
__device__ __forceinline__ void upk2(ull v, float& lo, float& hi) {
    asm("mov.b64 {%0,%1},%2;" : "=f"(lo), "=f"(hi) : "l"(v));
}
__device__ __forceinline__ ull ffma2(ull a, ull b, ull c) {
    ull d; asm("fma.rn.f32x2 %0,%1,%2,%3;" : "=l"(d) : "l"(a), "l"(b), "l"(c)); return d;
}

// sigmoid via MUFU (err ~1e-6). tanh(x) = 2*sig(2x)-1 (exact identity).
__device__ __forceinline__ float sig_(float x) {
    float e = __expf(-x);
    return __fdividef(1.f, 1.f + e);
}
__device__ __forceinline__ float tanh_(float x) {
    return 2.f * sig_(2.f * x) - 1.f;
}

// ============================================================================
// xgemm: xg[b,s, hh*4+q] = (bih+bhh)[q*64+hh] + Wih[q*64+hh,:] . hs[b,s,:]
// Grid 256 = (128 batch pairs) x (2 s-halves); 256 threads. Thread gq -> row
// q*64+hh (q=gq&3, hh=gq>>2) so writes are gq-consecutive = coalesced.
// FFMA2-issue-bound (~chip floor). Unchanged from R5.
// ============================================================================
__global__ __launch_bounds__(256, 1)
void xgemm(const float* __restrict__ hs, const float* __restrict__ Wih,
           const float* __restrict__ bih, const float* __restrict__ bhh,
           float* __restrict__ xg) {
    const int gq = threadIdx.x;
    const int q = gq & 3, hh = gq >> 2;
    const int row = q * HH + hh;
    const int b0 = (blockIdx.x >> 1) * 2;
    const int s0 = (blockIdx.x & 1) * (SS / 2);

    __shared__ float4 sh[2][16][16];   // [parity][chunk row][16 float4]

    ull w[32];
    {
        const float4* Wr = reinterpret_cast<const float4*>(Wih + row * HH);
#pragma unroll
        for (int k = 0; k < 16; k++) {
            float4 v = Wr[k];
            w[2 * k] = pk2(v.x, v.y);
            w[2 * k + 1] = pk2(v.z, v.w);
        }
    }
    const float bias = bih[row] + bhh[row];

    const int bb = gq >> 7, so = (gq >> 4) & 7, qq = gq & 15;
    const size_t ldb = ((size_t)(b0 + bb) * SS + s0 + so) * 16 + qq;  // float4 units
    const float4* hs4 = reinterpret_cast<const float4*>(hs);

    sh[0][bb * 8 + so][qq] = hs4[ldb];   // prime chunk 0

    int p = 0;
    const int NCH = (SS / 2) / 8;  // 256 chunks
    for (int ch = 0; ch < NCH; ++ch) {
        __syncthreads();
        float4 nxt;
        if (ch + 1 < NCH) nxt = hs4[ldb + (size_t)(ch + 1) * 128];

#pragma unroll
        for (int rp = 0; rp < 8; ++rp) {
            const int r0 = 2 * rp, r1 = r0 + 1;
            ull a0 = pk2(bias, 0.f);
            ull a1 = pk2(bias, 0.f);
            const ulonglong2* v0 = reinterpret_cast<const ulonglong2*>(sh[p][r0]);
            const ulonglong2* v1 = reinterpret_cast<const ulonglong2*>(sh[p][r1]);
#pragma unroll
            for (int k = 0; k < 16; k++) {
                ulonglong2 p0 = v0[k];
                ulonglong2 p1 = v1[k];
                a0 = ffma2(w[2 * k], p0.x, a0);
                a0 = ffma2(w[2 * k + 1], p0.y, a0);
                a1 = ffma2(w[2 * k], p1.x, a1);
                a1 = ffma2(w[2 * k + 1], p1.y, a1);
            }
            float l, h;
            upk2(a0, l, h); float sA = l + h;
            upk2(a1, l, h); float sB = l + h;
            xg[((size_t)(b0 + (r0 >> 3)) * SS + s0 + (size_t)ch * 8 + (r0 & 7)) * NG + gq] = sA;
            xg[((size_t)(b0 + (r1 >> 3)) * SS + s0 + (size_t)ch * 8 + (r1 & 7)) * NG + gq] = sB;
        }
        if (ch + 1 < NCH) sh[p ^ 1][bb * 8 + so][qq] = nxt;
        p ^= 1;
    }
}

// ============================================================================
// LSTM scan, occupancy-2 edition. 256 CTAs x 256 threads, 1 batch per CTA,
// TWO co-resident CTAs per SM hide each other's serial latency.
// Thread j: q=j&3 (gate i/f/g/o), hh=j>>2 (hidden unit), row=q*64+hh.
// Whh row in regs (32 ull = 64 regs; ~100 total -> occupancy 2).
// Gate exchange: 4 bfly shfls within the lane quad. One barrier/step.
// ============================================================================
template <bool L0>
__global__ __launch_bounds__(256, 2)
void lstm_scan(const float* __restrict__ xin,   // L0: x [B,S,1]; else xg [B,S,256]
               const float* __restrict__ Wih,   // L0 only: [256,1]
               const float* __restrict__ Whh,
               const float* __restrict__ bih, const float* __restrict__ bhh,
               float* __restrict__ hsout,
               float* __restrict__ hn, float* __restrict__ cn) {
    const int j = threadIdx.x;
    const int q = j & 3;
    const int hh = j >> 2;
    const int row = q * HH + hh;
    const int b = blockIdx.x;

    __shared__ float4 sh_h[2][16];   // [parity][64 floats]

    ull w[32];
    {
        const float4* Wr = reinterpret_cast<const float4*>(Whh + row * HH);
#pragma unroll
        for (int k = 0; k < 16; k++) {
            float4 v = Wr[k];
            w[2 * k] = pk2(v.x, v.y);
            w[2 * k + 1] = pk2(v.z, v.w);
        }
    }
    float w0 = 0.f, bias = 0.f;
    if (L0) { w0 = Wih[row]; bias = bih[row] + bhh[row]; }

    // activation params: A = m*sig(m*g) - d  (g-gate -> tanh)
    const float m0 = (q == 2) ? 2.f : 1.f;
    const float d0 = (q == 2) ? 1.f : 0.f;

    if (j < 16) sh_h[0][j] = make_float4(0.f, 0.f, 0.f, 0.f);

    // ---- x stream, depth-2 register prefetch ----
    float xc, xn;
    size_t xb;
    if (L0) {
        xb = (size_t)b * SS;            // scalar per step (uniform LDG)
        xc = xin[xb];
        xn = xin[xb + 1];
    } else {
        xb = (size_t)b * SS * NG + j;   // coalesced float per thread per step
        xc = xin[xb];
        xn = xin[xb + (size_t)NG];
    }
    __syncthreads();

    float c = 0.f;

    for (int t = 0; t < SS; ++t) {
        const int pr = t & 1;

        // prefetch t+2 early (covers DRAM/L2 latency across the step)
        float pf = 0.f;
        if (t + 2 < SS) pf = xin[xb + (L0 ? (size_t)(t + 2) : (size_t)(t + 2) * NG)];

        // ax for this step
        const float ax = L0 ? fmaf(w0, xc, bias) : xc;

        // g = ax + Whh . h_{t-1}  (two 16-deep chains)
        ull a0 = pk2(ax, 0.f);
        ull a1 = pk2(0.f, 0.f);
        const ulonglong2* vh = reinterpret_cast<const ulonglong2*>(sh_h[pr]);
#pragma unroll
        for (int k = 0; k < 8; k++) {
            ulonglong2 p0 = vh[k];
            ulonglong2 p1 = vh[8 + k];
            a0 = ffma2(w[2 * k], p0.x, a0);
            a0 = ffma2(w[2 * k + 1], p0.y, a0);
            a1 = ffma2(w[16 + 2 * k], p1.x, a1);
            a1 = ffma2(w[17 + 2 * k], p1.y, a1);
        }
        float l, h;
        upk2(a0, l, h); float s = l + h;
        upk2(a1, l, h); s += l + h;

        // activation (branchless per-thread constants)
        float A = m0 * sig_(m0 * s) - d0;

        // quad butterfly: gather all 4 gates of unit hh
        float Ax = __shfl_xor_sync(0xffffffffu, A, 1);    // gate q^1
        float By = __shfl_xor_sync(0xffffffffu, A, 2);    // gate q^2
        float Bz = __shfl_xor_sync(0xffffffffu, Ax, 2);   // gate q^3
        // val[d] = gate (q^d); select gate indices 0..3 (i,f,g,o)
        float iv = (q == 0) ? A : (q == 1) ? Ax : (q == 2) ? By : Bz;
        float fv = (q == 1) ? A : (q == 0) ? Ax : (q == 3) ? By : Bz;
        float gv = (q == 2) ? A : (q == 3) ? Ax : (q == 0) ? By : Bz;
        float ov = (q == 3) ? A : (q == 2) ? Ax : (q == 1) ? By : Bz;

        // identical update in all 4 lanes of the quad (deterministic)
        c = fv * c + iv * gv;
        float hv = ov * tanh_(c);

        if (q == 0) {
            reinterpret_cast<float*>(sh_h[pr ^ 1])[hh] = hv;
        } else if (q == 1) {
            hsout[((size_t)b * SS + t) * HH + hh] = hv;
            if (t == SS - 1) hn[b * HH + hh] = hv;
        } else if (q == 2) {
            if (t == SS - 1) cn[b * HH + hh] = c;
        }
        __syncthreads();   // h_t visible for step t+1

        xc = xn;
        xn = pf;
    }
}

// Final projection: thread-per-output, 16 consecutive LDG.128 per thread.
__global__ __launch_bounds__(256)
void proj_kernel(const float* __restrict__ hs, const float* __restrict__ Wlin,
                 const float* __restrict__ blin, float* __restrict__ y) {
    __shared__ float4 w[16];
    __shared__ float bsh;
    if (threadIdx.x < 16) w[threadIdx.x] = reinterpret_cast<const float4*>(Wlin)[threadIdx.x];
    if (threadIdx.x == 16) bsh = blin[0];
    __syncthreads();
    size_t o = (size_t)blockIdx.x * 256 + threadIdx.x;
    const float4* v = reinterpret_cast<const float4*>(hs + o * HH);
    float acc = 0.f;
#pragma unroll
    for (int k = 0; k < 16; k++) {
        float4 a = v[k];
        float4 b = w[k];
        acc += a.x * b.x + a.y * b.y + a.z * b.z + a.w * b.w;
    }
    y[o] = acc + bsh;
}

extern "C" void kernel_launch(void* const* d_in, const int* in_sizes, int n_in,
                              void* d_out, int out_size) {
    const float* x    = (const float*)d_in[0];
    const float* Wih0 = (const float*)d_in[1];
    const float* Whh0 = (const float*)d_in[2];
    const float* bih0 = (const float*)d_in[3];
    const float* bhh0 = (const float*)d_in[4];
    const float* Wih1 = (const float*)d_in[5];
    const float* Whh1 = (const float*)d_in[6];
    const float* bih1 = (const float*)d_in[7];
    const float* bhh1 = (const float*)d_in[8];
    const float* Wih2 = (const float*)d_in[9];
    const float* Whh2 = (const float*)d_in[10];
    const float* bih2 = (const float*)d_in[11];
    const float* bhh2 = (const float*)d_in[12];
    const float* Wlin = (const float*)d_in[13];
    const float* blin = (const float*)d_in[14];

    float* y  = (float*)d_out;                 // [B,S,1]
    float* hn = y + (size_t)BB * SS;           // [3,B,H]
    float* cn = hn + (size_t)3 * BB * HH;      // [3,B,H]

    float *buf0, *buf1, *xg;
    cudaGetSymbolAddress((void**)&buf0, g_buf0);
    cudaGetSymbolAddress((void**)&buf1, g_buf1);
    cudaGetSymbolAddress((void**)&xg,  g_xg);

    // Layer 0: inline scalar x (DIN=1)
    lstm_scan<true ><<<BB, 256>>>(x, Wih0, Whh0, bih0, bhh0, buf0, hn, cn);
    // Layer 1: precompute interleaved xg, then h-only scan
    xgemm<<<BB, 256>>>(buf0, Wih1, bih1, bhh1, xg);
    lstm_scan<false><<<BB, 256>>>(xg, Wih1, Whh1, bih1, bhh1, buf1,
                                  hn + BB * HH, cn + BB * HH);
    // Layer 2
    xgemm<<<BB, 256>>>(buf1, Wih2, bih2, bhh2, xg);
    lstm_scan<false><<<BB, 256>>>(xg, Wih2, Whh2, bih2, bhh2, buf0,
                                  hn + 2 * BB * HH, cn + 2 * BB * HH);

    proj_kernel<<<(BB * SS) / 256, 256>>>(buf0, Wlin, blin, y);
}